// round 10
// baseline (speedup 1.0000x reference)
#include <cuda_runtime.h>

#define BB   2
#define NN   512
#define OBJ  320
#define GEO  6
#define LANG 256
#define HID  256
#define ROWS (BB*NN)   // 1024

#define C2 0.3989423f
#define C4 -0.0664904f
#define TWO_C2 0.79788456f

typedef unsigned long long u64;

__device__ __forceinline__ u64 pk2(float lo, float hi) {
    u64 r; asm("mov.b64 %0, {%1, %2};" : "=l"(r) : "f"(lo), "f"(hi)); return r;
}
__device__ __forceinline__ void upk2(float& lo, float& hi, u64 v) {
    asm("mov.b64 {%0, %1}, %2;" : "=f"(lo), "=f"(hi) : "l"(v));
}
__device__ __forceinline__ u64 ffma2(u64 a, u64 b, u64 c) {
    u64 d; asm("fma.rn.f32x2 %0, %1, %2, %3;" : "=l"(d) : "l"(a), "l"(b), "l"(c)); return d;
}

// L2-resident scratch
__device__ float g_emb[ROWS*OBJ];      // normalized embeddings
__device__ float g_hl [BB*HID];        // lang_n@Wl + b1
__device__ float g_FAt[HID*ROWS];      // [h][i]: 2*c2*W2[h]*hi[i,h]
__device__ float g_FBt[HID*ROWS];      // [h][j]: hj[j,h]
__device__ float g_Si [4*ROWS];        // per-h-quarter partials
__device__ float g_Sj [4*ROWS];
__device__ float g_sc [2*ROWS*NN];     // cross-score K-half partials
__device__ float g_pw [ROWS*NN];       // softmax pair weights
__device__ float g_cp [8][ROWS*OBJ];   // context j-split partials

// ============ K0: normalize utterance, hl = lang_n@Wl + b1 ============
__global__ void __launch_bounds__(512) k_lang(const float* __restrict__ utter,
                                              const float* __restrict__ W1,
                                              const float* __restrict__ b1) {
    int b = blockIdx.x, t = threadIdx.x;   // 512 threads
    int h = t & 255, half = t >> 8;
    __shared__ float ls[LANG];
    __shared__ float red[8];
    __shared__ float part[2][HID];
    float v = 0.f;
    if (half == 0) {
        v = utter[b*LANG + t];
        float ss = v*v;
        #pragma unroll
        for (int o = 16; o; o >>= 1) ss += __shfl_xor_sync(0xffffffffu, ss, o);
        if ((t & 31) == 0) red[t >> 5] = ss;
    }
    __syncthreads();
    if (half == 0) {
        float tot = 0.f;
        #pragma unroll
        for (int w = 0; w < 8; w++) tot += red[w];
        ls[t] = v * rsqrtf(tot);
    }
    __syncthreads();
    float acc = (half == 0) ? b1[h] : 0.f;
    const float* Wl = W1 + (2*OBJ + GEO)*HID + h;
    int l0 = half * 128;
    #pragma unroll 4
    for (int l = 0; l < 128; l++) acc = fmaf(ls[l0 + l], Wl[(l0 + l)*HID], acc);
    part[half][h] = acc;
    __syncthreads();
    if (half == 0) g_hl[b*HID + h] = part[0][h] + part[1][h];
}

// ============ K0b: l2-normalize object embeddings ============
__global__ void k_norm(const float* __restrict__ emb) {
    int row = blockIdx.x;
    int t = threadIdx.x;              // 128 threads
    const float* src = emb + row*OBJ;
    float v0 = src[t];
    float v1 = src[t+128];
    float v2 = (t < 64) ? src[t+256] : 0.f;
    float ss = v0*v0 + v1*v1 + v2*v2;
    #pragma unroll
    for (int o = 16; o; o >>= 1) ss += __shfl_xor_sync(0xffffffffu, ss, o);
    __shared__ float red[4];
    if ((t & 31) == 0) red[t >> 5] = ss;
    __syncthreads();
    float inv = rsqrtf(red[0] + red[1] + red[2] + red[3]);
    float* dst = g_emb + row*OBJ;
    dst[t]       = v0*inv;
    dst[t+128]   = v1*inv;
    if (t < 64) dst[t+256] = v2*inv;
}

// ============ K1: projections + features + Si/Sj quarter-partials ============
// grid 256 = 64 row-tiles (16 rows) x 4 h-quarters (64 h). 256 threads.
#define EPITCH 324
__global__ void __launch_bounds__(256) k_proj(const float* __restrict__ geom,
                                              const float* __restrict__ W1,
                                              const float* __restrict__ W2) {
    __shared__ __align__(16) float e4[16*EPITCH];  // 20.7 KB staged rows
    __shared__ __align__(16) float2 ep[OBJ][8];    // 20 KB row-pairs
    __shared__ __align__(16) float2 gp[GEO][8];
    __shared__ float red_si[8][4], red_sj[8][4];

    int bx = blockIdx.x;
    int rowtile = bx >> 2, hq = bx & 3;
    int row0 = rowtile * 16;
    int h0 = hq * 64;
    int b = row0 >> 9;
    int t = threadIdx.x;
    int lane = t & 31, warp = t >> 5;
    int hh = t & 63, rp2 = t >> 6;                 // rp2: 2 row-pairs
    int h = h0 + hh;

    // stage normalized rows (coalesced float4) + geometry pairs
    {
        const float4* src = (const float4*)(g_emb + row0*OBJ);
        for (int idx = t; idx < 16*80; idx += 256) {
            int r = idx / 80, c = idx - r*80;
            *(float4*)&e4[r*EPITCH + c*4] = src[idx];
        }
    }
    if (t < GEO*8) {
        int d = t >> 3, p = t & 7;
        gp[d][p] = make_float2(geom[(row0 + 2*p)*GEO + d], geom[(row0 + 2*p + 1)*GEO + d]);
    }
    __syncthreads();
    // repack to row-pairs
    for (int idx = t; idx < OBJ*8; idx += 256) {
        int d = idx >> 3, p = idx & 7;
        ep[d][p] = make_float2(e4[(2*p)*EPITCH + d], e4[(2*p+1)*EPITCH + d]);
    }
    __syncthreads();

    // main projection: thread handles 2 row-pairs (rp2*2, rp2*2+1) for its h
    u64 ai[2], aj[2];
    ai[0] = ai[1] = aj[0] = aj[1] = 0ull;
    const float* Wi = W1 + h;
    const float* Wj = W1 + OBJ*HID + h;
    #pragma unroll 4
    for (int d = 0; d < OBJ; d++) {
        float wi = Wi[d*HID];
        float wj = Wj[d*HID];
        u64 wip = pk2(wi, wi), wjp = pk2(wj, wj);
        ulonglong2 E = *(const ulonglong2*)&ep[d][rp2*2];
        ai[0] = ffma2(E.x, wip, ai[0]);  aj[0] = ffma2(E.x, wjp, aj[0]);
        ai[1] = ffma2(E.y, wip, ai[1]);  aj[1] = ffma2(E.y, wjp, aj[1]);
    }
    const float* Wg = W1 + 2*OBJ*HID + h;
    #pragma unroll
    for (int g = 0; g < GEO; g++) {
        float wg = Wg[g*HID];
        u64 wgp = pk2(wg, wg), wgm = pk2(-wg, -wg);
        ulonglong2 G = *(const ulonglong2*)&gp[g][rp2*2];
        ai[0] = ffma2(G.x, wgm, ai[0]);  aj[0] = ffma2(G.x, wgp, aj[0]);
        ai[1] = ffma2(G.y, wgm, ai[1]);  aj[1] = ffma2(G.y, wgp, aj[1]);
    }

    // epilogue: features + per-row partial reductions (4 local rows)
    float w2v = W2[h];
    float hlv = g_hl[b*HID + h];
    float sir[4], sjr[4];
    #pragma unroll
    for (int p = 0; p < 2; p++) {
        int P = rp2*2 + p;
        float a0, a1, j0v, j1v;
        upk2(a0, a1, ai[p]);
        upk2(j0v, j1v, aj[p]);
        float hv0 = a0 + hlv, hv1 = a1 + hlv;
        *(float2*)&g_FAt[h*ROWS + row0 + 2*P] = make_float2(TWO_C2*w2v*hv0, TWO_C2*w2v*hv1);
        *(float2*)&g_FBt[h*ROWS + row0 + 2*P] = make_float2(j0v, j1v);
        float u0 = hv0*hv0, u1 = hv1*hv1;
        sir[2*p]   = w2v * fmaf(u0, fmaf(C4, u0, C2), 0.5f*hv0);
        sir[2*p+1] = w2v * fmaf(u1, fmaf(C4, u1, C2), 0.5f*hv1);
        float v0 = j0v*j0v, v1 = j1v*j1v;
        sjr[2*p]   = w2v * fmaf(v0, fmaf(C4, v0, C2), 0.5f*j0v);
        sjr[2*p+1] = w2v * fmaf(v1, fmaf(C4, v1, C2), 0.5f*j1v);
    }
    #pragma unroll
    for (int lr = 0; lr < 4; lr++) {
        float si = sir[lr], sj = sjr[lr];
        #pragma unroll
        for (int o = 16; o; o >>= 1) {
            si += __shfl_xor_sync(0xffffffffu, si, o);
            sj += __shfl_xor_sync(0xffffffffu, sj, o);
        }
        if (lane == 0) { red_si[warp][lr] = si; red_sj[warp][lr] = sj; }
    }
    __syncthreads();
    // row r local: group rp2r = r>>2 covered by warps 2*rp2r, 2*rp2r+1
    if (t < 16) {
        int r = t;
        int g2 = r >> 2, lr = r & 3;
        g_Si[hq*ROWS + row0 + r] = red_si[2*g2][lr] + red_si[2*g2+1][lr];
    } else if (t < 32) {
        int r = t - 16;
        int g2 = r >> 2, lr = r & 3;
        g_Sj[hq*ROWS + row0 + r] = red_sj[2*g2][lr] + red_sj[2*g2+1][lr];
    }
}

// ============ K2: cross GEMM K-split  g_sc[kh][i,j] = sum_{h in half} FAt*FBt ============
// grid (8, 8, 4): z = b*2 + kh. 64x64 tile, K=128 in 8 chunks of 16.
__global__ void __launch_bounds__(256) k_gemm() {
    __shared__ __align__(16) float2 Asp[16][64];
    __shared__ __align__(16) float  Bs [16][64];
    int t = threadIdx.x;
    int tx = t & 15, ty = t >> 4;
    int lk = t >> 4, l4 = (t & 15) * 4;
    int z  = blockIdx.z;
    int b  = z >> 1, kh = z & 1;
    int i0 = b*NN + blockIdx.y*64;
    int j0 = b*NN + blockIdx.x*64;

    const float* pa = g_FAt + (kh*128 + lk)*ROWS + i0 + l4;
    const float* pb = g_FBt + (kh*128 + lk)*ROWS + j0 + l4;

    u64 acc2[4][2];
    #pragma unroll
    for (int r = 0; r < 4; r++) { acc2[r][0] = 0ull; acc2[r][1] = 0ull; }

    float4 a4 = *(const float4*)pa;
    float4 b4 = *(const float4*)pb;

    #pragma unroll 1
    for (int ch = 0; ch < 8; ch++) {
        *(float4*)&Asp[lk][l4]     = make_float4(a4.x, a4.x, a4.y, a4.y);
        *(float4*)&Asp[lk][l4 + 2] = make_float4(a4.z, a4.z, a4.w, a4.w);
        *(float4*)&Bs[lk][l4] = b4;
        __syncthreads();
        if (ch < 7) {
            a4 = *(const float4*)(pa + (ch+1)*16*ROWS);
            b4 = *(const float4*)(pb + (ch+1)*16*ROWS);
        }
        #pragma unroll
        for (int k = 0; k < 16; k++) {
            ulonglong2 aA = *(const ulonglong2*)&Asp[k][ty*4];
            ulonglong2 aB = *(const ulonglong2*)&Asp[k][ty*4 + 2];
            ulonglong2 bP = *(const ulonglong2*)&Bs[k][tx*4];
            acc2[0][0] = ffma2(aA.x, bP.x, acc2[0][0]);
            acc2[0][1] = ffma2(aA.x, bP.y, acc2[0][1]);
            acc2[1][0] = ffma2(aA.y, bP.x, acc2[1][0]);
            acc2[1][1] = ffma2(aA.y, bP.y, acc2[1][1]);
            acc2[2][0] = ffma2(aB.x, bP.x, acc2[2][0]);
            acc2[2][1] = ffma2(aB.x, bP.y, acc2[2][1]);
            acc2[3][0] = ffma2(aB.y, bP.x, acc2[3][0]);
            acc2[3][1] = ffma2(aB.y, bP.y, acc2[3][1]);
        }
        __syncthreads();
    }

    int irow = i0 + ty*4;
    int jcol = blockIdx.x*64 + tx*4;
    float* dst = g_sc + (size_t)kh*ROWS*NN;
    #pragma unroll
    for (int r = 0; r < 4; r++) {
        float c0, c1, c2v, c3;
        upk2(c0, c1, acc2[r][0]);
        upk2(c2v, c3, acc2[r][1]);
        *(float4*)&dst[(irow + r)*NN + jcol] = make_float4(c0, c1, c2v, c3);
    }
}

// ============ K3: softmax + relation_scores ============
__global__ void k_soft(const float* __restrict__ b2p, float* __restrict__ out_scores) {
    int row = blockIdx.x;
    int b = row >> 9;
    int t = threadIdx.x;              // 128 threads, 4 cols each
    int lane = t & 31, warp = t >> 5;
    __shared__ float rm[4], rs[4], rss[4];

    float4 cA = *(const float4*)&g_sc[row*NN + t*4];
    float4 cB = *(const float4*)&g_sc[(size_t)ROWS*NN + row*NN + t*4];
    float s0 = cA.x + cB.x, s1 = cA.y + cB.y, s2 = cA.z + cB.z, s3 = cA.w + cB.w;
    #pragma unroll
    for (int q = 0; q < 4; q++) {
        float4 jq = *(const float4*)&g_Sj[q*ROWS + b*NN + t*4];
        s0 += jq.x; s1 += jq.y; s2 += jq.z; s3 += jq.w;
    }

    float m = fmaxf(fmaxf(s0, s1), fmaxf(s2, s3));
    #pragma unroll
    for (int o = 16; o; o >>= 1) m = fmaxf(m, __shfl_xor_sync(0xffffffffu, m, o));
    if (lane == 0) rm[warp] = m;
    __syncthreads();
    m = fmaxf(fmaxf(rm[0], rm[1]), fmaxf(rm[2], rm[3]));

    float e0 = __expf(s0 - m), e1 = __expf(s1 - m), e2 = __expf(s2 - m), e3 = __expf(s3 - m);
    float se  = (e0 + e1) + (e2 + e3);
    float ses = fmaf(e0, s0, fmaf(e1, s1, fmaf(e2, s2, e3*s3)));
    #pragma unroll
    for (int o = 16; o; o >>= 1) {
        se  += __shfl_xor_sync(0xffffffffu, se,  o);
        ses += __shfl_xor_sync(0xffffffffu, ses, o);
    }
    if (lane == 0) { rs[warp] = se; rss[warp] = ses; }
    __syncthreads();
    float setot  = (rs[0]  + rs[1])  + (rs[2]  + rs[3]);
    float sestot = (rss[0] + rss[1]) + (rss[2] + rss[3]);

    float inv = __fdividef(1.f, setot);
    float4 pw = make_float4(e0*inv, e1*inv, e2*inv, e3*inv);
    *(float4*)&g_pw[row*NN + t*4] = pw;
    if (t == 0) out_scores[row] = sestot*inv + g_Si[row] + g_Si[ROWS + row]
                                + g_Si[2*ROWS + row] + g_Si[3*ROWS + row] + b2p[0];
}

// ============ K4: context partials  g_cp[jh] = pw-slice @ emb  ============
// grid (32 = 4 d-tiles x 8 j-splits, 16 i-tiles of 64 rows) = 512 CTAs, 256 thr.
// thread: ig = t>>3 -> rows 2ig, 2ig+1;  dx = t&7 -> 10 d-cols (5 f32x2 pairs).
// pw stored as duplicated (w,w) float2 pairs; row pitch 37 -> conflict-free.
__global__ void __launch_bounds__(256) k_ctx() {
    __shared__ __align__(16) float  e_s[32][80];   // 10 KB
    __shared__ __align__(8)  float2 pwp[64][37];   // 18.9 KB dup pairs
    int t = threadIdx.x;
    int ig = t >> 3, dx = t & 7;
    int dt = blockIdx.x & 3, jh = blockIdx.x >> 2;
    int it = blockIdx.y;
    int i0 = it * 64;                  // global row
    int b  = it >> 3;
    int d0 = dt * 80;
    int dbase = dx * 10;
    int r0 = 2*ig, r1 = 2*ig + 1;

    u64 acc0[5], acc1[5];
    #pragma unroll
    for (int q = 0; q < 5; q++) { acc0[q] = 0ull; acc1[q] = 0ull; }

    #pragma unroll 1
    for (int ch = 0; ch < 2; ch++) {
        int j0 = jh*64 + ch*32;        // j within batch
        // load e tile: 32 j x 80 d
        #pragma unroll
        for (int pass = 0; pass < 5; pass++) {
            int idx = t + pass*256;    // 1280 float2
            int jr = idx / 40, dc = idx - jr*40;
            *(float2*)&e_s[jr][dc*2] =
                *(const float2*)&g_emb[(size_t)(b*NN + j0 + jr)*OBJ + d0 + dc*2];
        }
        // load pw tile: 64 i x 32 j, duplicated into (w,w) pairs
        {
            int pr = t >> 2, pc = (t & 3) * 8;
            float4 v0 = *(const float4*)&g_pw[(size_t)(i0 + pr)*NN + j0 + pc];
            float4 v1 = *(const float4*)&g_pw[(size_t)(i0 + pr)*NN + j0 + pc + 4];
            pwp[pr][pc+0] = make_float2(v0.x, v0.x);
            pwp[pr][pc+1] = make_float2(v0.y, v0.y);
            pwp[pr][pc+2] = make_float2(v0.z, v0.z);
            pwp[pr][pc+3] = make_float2(v0.w, v0.w);
            pwp[pr][pc+4] = make_float2(v1.x, v1.x);
            pwp[pr][pc+5] = make_float2(v1.y, v1.y);
            pwp[pr][pc+6] = make_float2(v1.z, v1.z);
            pwp[pr][pc+7] = make_float2(v1.w, v1.w);
        }
        __syncthreads();
        #pragma unroll
        for (int jk = 0; jk < 32; jk++) {
            u64 p0 = *(const u64*)&pwp[r0][jk];
            u64 p1 = *(const u64*)&pwp[r1][jk];
            #pragma unroll
            for (int q = 0; q < 5; q++) {
                u64 e2 = *(const u64*)&e_s[jk][dbase + 2*q];
                acc0[q] = ffma2(p0, e2, acc0[q]);
                acc1[q] = ffma2(p1, e2, acc1[q]);
            }
        }
        __syncthreads();
    }

    float* o0 = &g_cp[jh][(size_t)(i0 + r0)*OBJ + d0 + dbase];
    float* o1 = &g_cp[jh][(size_t)(i0 + r1)*OBJ + d0 + dbase];
    #pragma unroll
    for (int q = 0; q < 5; q++) {
        float x0, x1;
        upk2(x0, x1, acc0[q]);
        *(float2*)&o0[2*q] = make_float2(x0, x1);
        upk2(x0, x1, acc1[q]);
        *(float2*)&o1[2*q] = make_float2(x0, x1);
    }
}

// ============ K5: combine j-split partials ============
__global__ void __launch_bounds__(256) k_comb(float* __restrict__ out_ctx) {
    int idx = (blockIdx.x * 256 + threadIdx.x) * 4;      // over ROWS*OBJ floats
    float4 s = *(const float4*)&g_cp[0][idx];
    #pragma unroll
    for (int q = 1; q < 8; q++) {
        float4 v = *(const float4*)&g_cp[q][idx];
        s.x += v.x; s.y += v.y; s.z += v.z; s.w += v.w;
    }
    *(float4*)&out_ctx[idx] = s;
}

extern "C" void kernel_launch(void* const* d_in, const int* in_sizes, int n_in,
                              void* d_out, int out_size) {
    (void)in_sizes; (void)n_in; (void)out_size;
    const float* emb   = (const float*)d_in[0];
    const float* geom  = (const float*)d_in[1];
    const float* utter = (const float*)d_in[2];
    const float* W1    = (const float*)d_in[3];
    const float* b1    = (const float*)d_in[4];
    const float* W2    = (const float*)d_in[5];
    const float* b2    = (const float*)d_in[6];
    float* out = (float*)d_out;            // [0,1024): relation_scores; then context

    k_lang<<<BB, 512>>>(utter, W1, b1);
    k_norm<<<ROWS, 128>>>(emb);
    k_proj<<<256, 256>>>(geom, W1, W2);
    {
        dim3 g(NN/64, NN/64, 2*BB);        // profiled launch (index 3)
        k_gemm<<<g, 256>>>();
    }
    k_soft<<<ROWS, 128>>>(b2, out);
    {
        dim3 g(32, 16);
        k_ctx<<<g, 256>>>();
    }
    k_comb<<<(ROWS*OBJ)/1024, 256>>>(out + ROWS);
}

// round 12
// speedup vs baseline: 1.0319x; 1.0319x over previous
#include <cuda_runtime.h>

#define BB   2
#define NN   512
#define OBJ  320
#define GEO  6
#define LANG 256
#define HID  256
#define ROWS (BB*NN)   // 1024

#define C2 0.3989423f
#define C4 -0.0664904f
#define TWO_C2 0.79788456f

typedef unsigned long long u64;

__device__ __forceinline__ u64 pk2(float lo, float hi) {
    u64 r; asm("mov.b64 %0, {%1, %2};" : "=l"(r) : "f"(lo), "f"(hi)); return r;
}
__device__ __forceinline__ void upk2(float& lo, float& hi, u64 v) {
    asm("mov.b64 {%0, %1}, %2;" : "=f"(lo), "=f"(hi) : "l"(v));
}
__device__ __forceinline__ u64 ffma2(u64 a, u64 b, u64 c) {
    u64 d; asm("fma.rn.f32x2 %0, %1, %2, %3;" : "=l"(d) : "l"(a), "l"(b), "l"(c)); return d;
}

// L2-resident scratch
__device__ float g_emb[ROWS*OBJ];      // normalized embeddings
__device__ float g_FAt[HID*ROWS];      // [h][i]: 2*c2*W2[h]*hi[i,h]
__device__ float g_FBt[HID*ROWS];      // [h][j]: hj[j,h]
__device__ float g_Si [4*ROWS];        // per-h-quarter partials
__device__ float g_Sj [4*ROWS];
__device__ float g_sc [2*ROWS*NN];     // cross-score K-half partials
__device__ float g_pw [ROWS*NN];       // softmax pair weights
__device__ float g_cp [8][ROWS*OBJ];   // context j-split partials

// ============ K1: norm(emb) + norm(utter)+hl + projections + Si/Sj ============
// grid 256 = 64 row-tiles (16 rows) x 4 h-quarters (64 h). 256 threads.
#define EPITCH 324
__global__ void __launch_bounds__(256) k_proj(const float* __restrict__ emb_raw,
                                              const float* __restrict__ geom,
                                              const float* __restrict__ utter,
                                              const float* __restrict__ W1,
                                              const float* __restrict__ b1,
                                              const float* __restrict__ W2) {
    __shared__ __align__(16) float e4[16*EPITCH];  // 20.7 KB staged rows
    __shared__ __align__(16) float2 ep[OBJ][8];    // 20 KB row-pairs
    __shared__ __align__(16) float2 gp[GEO][8];
    __shared__ float ls[LANG];
    __shared__ float redl[8];
    __shared__ float hlp[4][64];
    __shared__ float red_si[8][4], red_sj[8][4];

    int bx = blockIdx.x;
    int rowtile = bx >> 2, hq = bx & 3;
    int row0 = rowtile * 16;
    int h0 = hq * 64;
    int b = row0 >> 9;
    int t = threadIdx.x;
    int lane = t & 31, warp = t >> 5;
    int hh = t & 63, rp2 = t >> 6;                 // h-index, 2-row-pair group
    int h = h0 + hh;

    // stage raw emb rows (coalesced float4)
    {
        const float4* src = (const float4*)(emb_raw + row0*OBJ);
        for (int idx = t; idx < 16*80; idx += 256) {
            int r = idx / 80, c = idx - r*80;
            *(float4*)&e4[r*EPITCH + c*4] = src[idx];
        }
    }
    // utterance sum-of-squares
    float lv = utter[b*LANG + t];
    {
        float ss = lv*lv;
        #pragma unroll
        for (int o = 16; o; o >>= 1) ss += __shfl_xor_sync(0xffffffffu, ss, o);
        if (lane == 0) redl[warp] = ss;
    }
    __syncthreads();

    // normalize emb rows: warp w owns rows w, w+8
    #pragma unroll
    for (int rr = 0; rr < 2; rr++) {
        int r = warp + rr*8;
        float ss = 0.f;
        for (int d = lane; d < OBJ; d += 32) { float v = e4[r*EPITCH + d]; ss = fmaf(v, v, ss); }
        #pragma unroll
        for (int o = 16; o; o >>= 1) ss += __shfl_xor_sync(0xffffffffu, ss, o);
        float inv = rsqrtf(ss);
        float* gdst = g_emb + (row0 + r)*OBJ;
        for (int d = lane; d < OBJ; d += 32) {
            float v = e4[r*EPITCH + d] * inv;
            e4[r*EPITCH + d] = v;
            if (hq == 0) gdst[d] = v;
        }
    }
    // normalized utterance
    {
        float tot = 0.f;
        #pragma unroll
        for (int w = 0; w < 8; w++) tot += redl[w];
        ls[t] = lv * rsqrtf(tot);
    }
    __syncthreads();

    // hl partial: 4 threads per h, each sums 64 l's
    {
        float acc = (rp2 == 0) ? b1[h] : 0.f;
        const float* Wl = W1 + (size_t)(2*OBJ + GEO + rp2*64)*HID + h;
        #pragma unroll 8
        for (int l = 0; l < 64; l++) acc = fmaf(ls[rp2*64 + l], Wl[l*HID], acc);
        hlp[rp2][hh] = acc;
    }
    // build pair layouts
    for (int idx = t; idx < OBJ*8; idx += 256) {
        int d = idx >> 3, p = idx & 7;
        ep[d][p] = make_float2(e4[(2*p)*EPITCH + d], e4[(2*p+1)*EPITCH + d]);
    }
    if (t < GEO*8) {
        int d = t >> 3, p = t & 7;
        gp[d][p] = make_float2(geom[(row0 + 2*p)*GEO + d], geom[(row0 + 2*p + 1)*GEO + d]);
    }
    __syncthreads();

    float hlv = (hlp[0][hh] + hlp[1][hh]) + (hlp[2][hh] + hlp[3][hh]);

    // main projection: thread handles 2 row-pairs for its h
    u64 ai[2], aj[2];
    ai[0] = ai[1] = aj[0] = aj[1] = 0ull;
    const float* Wi = W1 + h;
    const float* Wj = W1 + OBJ*HID + h;
    #pragma unroll 4
    for (int d = 0; d < OBJ; d++) {
        float wi = Wi[d*HID];
        float wj = Wj[d*HID];
        u64 wip = pk2(wi, wi), wjp = pk2(wj, wj);
        ulonglong2 E = *(const ulonglong2*)&ep[d][rp2*2];
        ai[0] = ffma2(E.x, wip, ai[0]);  aj[0] = ffma2(E.x, wjp, aj[0]);
        ai[1] = ffma2(E.y, wip, ai[1]);  aj[1] = ffma2(E.y, wjp, aj[1]);
    }
    const float* Wg = W1 + 2*OBJ*HID + h;
    #pragma unroll
    for (int g = 0; g < GEO; g++) {
        float wg = Wg[g*HID];
        u64 wgp = pk2(wg, wg), wgm = pk2(-wg, -wg);
        ulonglong2 G = *(const ulonglong2*)&gp[g][rp2*2];
        ai[0] = ffma2(G.x, wgm, ai[0]);  aj[0] = ffma2(G.x, wgp, aj[0]);
        ai[1] = ffma2(G.y, wgm, ai[1]);  aj[1] = ffma2(G.y, wgp, aj[1]);
    }

    // epilogue: features + quarter partial reductions
    float w2v = W2[h];
    float sir[4], sjr[4];
    #pragma unroll
    for (int p = 0; p < 2; p++) {
        int P = rp2*2 + p;
        float a0, a1, j0v, j1v;
        upk2(a0, a1, ai[p]);
        upk2(j0v, j1v, aj[p]);
        float hv0 = a0 + hlv, hv1 = a1 + hlv;
        *(float2*)&g_FAt[h*ROWS + row0 + 2*P] = make_float2(TWO_C2*w2v*hv0, TWO_C2*w2v*hv1);
        *(float2*)&g_FBt[h*ROWS + row0 + 2*P] = make_float2(j0v, j1v);
        float u0 = hv0*hv0, u1 = hv1*hv1;
        sir[2*p]   = w2v * fmaf(u0, fmaf(C4, u0, C2), 0.5f*hv0);
        sir[2*p+1] = w2v * fmaf(u1, fmaf(C4, u1, C2), 0.5f*hv1);
        float v0 = j0v*j0v, v1 = j1v*j1v;
        sjr[2*p]   = w2v * fmaf(v0, fmaf(C4, v0, C2), 0.5f*j0v);
        sjr[2*p+1] = w2v * fmaf(v1, fmaf(C4, v1, C2), 0.5f*j1v);
    }
    #pragma unroll
    for (int lr = 0; lr < 4; lr++) {
        float si = sir[lr], sj = sjr[lr];
        #pragma unroll
        for (int o = 16; o; o >>= 1) {
            si += __shfl_xor_sync(0xffffffffu, si, o);
            sj += __shfl_xor_sync(0xffffffffu, sj, o);
        }
        if (lane == 0) { red_si[warp][lr] = si; red_sj[warp][lr] = sj; }
    }
    __syncthreads();
    if (t < 16) {
        int r = t;
        int g2 = r >> 2, lr = r & 3;
        g_Si[hq*ROWS + row0 + r] = red_si[2*g2][lr] + red_si[2*g2+1][lr];
    } else if (t < 32) {
        int r = t - 16;
        int g2 = r >> 2, lr = r & 3;
        g_Sj[hq*ROWS + row0 + r] = red_sj[2*g2][lr] + red_sj[2*g2+1][lr];
    }
}

// ============ K2: cross GEMM K-split, B in double-buffered smem, A via L1 LDG ============
// grid (8, 8, 4): z = b*2 + kh. 64x64 tile, K=128 in 8 chunks of 16.
__global__ void __launch_bounds__(256) k_gemm() {
    __shared__ __align__(16) float Bs[2][16][64];  // 8 KB
    int t = threadIdx.x;
    int tx = t & 15, ty = t >> 4;
    int lk = t >> 4, l4 = (t & 15) * 4;
    int z  = blockIdx.z;
    int b  = z >> 1, kh = z & 1;
    int i0 = b*NN + blockIdx.y*64;
    int j0 = b*NN + blockIdx.x*64;
    int kbase0 = kh*128;

    const float* pb = g_FBt + (size_t)(kbase0 + lk)*ROWS + j0 + l4;
    const float* pa = g_FAt + (size_t)kbase0*ROWS + i0 + ty*4;

    u64 acc2[4][2];
    #pragma unroll
    for (int r = 0; r < 4; r++) { acc2[r][0] = 0ull; acc2[r][1] = 0ull; }

    float4 b4 = *(const float4*)pb;
    *(float4*)&Bs[0][lk][l4] = b4;
    __syncthreads();

    #pragma unroll 1
    for (int ch = 0; ch < 8; ch++) {
        int cur = ch & 1;
        if (ch < 7) b4 = *(const float4*)(pb + (size_t)(ch+1)*16*ROWS);
        #pragma unroll
        for (int k = 0; k < 16; k++) {
            float4 av = *(const float4*)(pa + (size_t)(ch*16 + k)*ROWS);
            ulonglong2 bP = *(const ulonglong2*)&Bs[cur][k][tx*4];
            u64 a0 = pk2(av.x, av.x);
            u64 a1 = pk2(av.y, av.y);
            u64 a2 = pk2(av.z, av.z);
            u64 a3 = pk2(av.w, av.w);
            acc2[0][0] = ffma2(a0, bP.x, acc2[0][0]);
            acc2[0][1] = ffma2(a0, bP.y, acc2[0][1]);
            acc2[1][0] = ffma2(a1, bP.x, acc2[1][0]);
            acc2[1][1] = ffma2(a1, bP.y, acc2[1][1]);
            acc2[2][0] = ffma2(a2, bP.x, acc2[2][0]);
            acc2[2][1] = ffma2(a2, bP.y, acc2[2][1]);
            acc2[3][0] = ffma2(a3, bP.x, acc2[3][0]);
            acc2[3][1] = ffma2(a3, bP.y, acc2[3][1]);
        }
        if (ch < 7) {
            *(float4*)&Bs[cur ^ 1][lk][l4] = b4;
            __syncthreads();
        }
    }

    int irow = i0 + ty*4;
    int jcol = blockIdx.x*64 + tx*4;
    float* dst = g_sc + (size_t)kh*ROWS*NN;
    #pragma unroll
    for (int r = 0; r < 4; r++) {
        float c0, c1, c2v, c3;
        upk2(c0, c1, acc2[r][0]);
        upk2(c2v, c3, acc2[r][1]);
        *(float4*)&dst[(irow + r)*NN + jcol] = make_float4(c0, c1, c2v, c3);
    }
}

// ============ K3: softmax + relation_scores ============
__global__ void k_soft(const float* __restrict__ b2p, float* __restrict__ out_scores) {
    int row = blockIdx.x;
    int b = row >> 9;
    int t = threadIdx.x;              // 128 threads, 4 cols each
    int lane = t & 31, warp = t >> 5;
    __shared__ float rm[4], rs[4], rss[4];

    float4 cA = *(const float4*)&g_sc[row*NN + t*4];
    float4 cB = *(const float4*)&g_sc[(size_t)ROWS*NN + row*NN + t*4];
    float s0 = cA.x + cB.x, s1 = cA.y + cB.y, s2 = cA.z + cB.z, s3 = cA.w + cB.w;
    #pragma unroll
    for (int q = 0; q < 4; q++) {
        float4 jq = *(const float4*)&g_Sj[q*ROWS + b*NN + t*4];
        s0 += jq.x; s1 += jq.y; s2 += jq.z; s3 += jq.w;
    }

    float m = fmaxf(fmaxf(s0, s1), fmaxf(s2, s3));
    #pragma unroll
    for (int o = 16; o; o >>= 1) m = fmaxf(m, __shfl_xor_sync(0xffffffffu, m, o));
    if (lane == 0) rm[warp] = m;
    __syncthreads();
    m = fmaxf(fmaxf(rm[0], rm[1]), fmaxf(rm[2], rm[3]));

    float e0 = __expf(s0 - m), e1 = __expf(s1 - m), e2 = __expf(s2 - m), e3 = __expf(s3 - m);
    float se  = (e0 + e1) + (e2 + e3);
    float ses = fmaf(e0, s0, fmaf(e1, s1, fmaf(e2, s2, e3*s3)));
    #pragma unroll
    for (int o = 16; o; o >>= 1) {
        se  += __shfl_xor_sync(0xffffffffu, se,  o);
        ses += __shfl_xor_sync(0xffffffffu, ses, o);
    }
    if (lane == 0) { rs[warp] = se; rss[warp] = ses; }
    __syncthreads();
    float setot  = (rs[0]  + rs[1])  + (rs[2]  + rs[3]);
    float sestot = (rss[0] + rss[1]) + (rss[2] + rss[3]);

    float inv = __fdividef(1.f, setot);
    float4 pw = make_float4(e0*inv, e1*inv, e2*inv, e3*inv);
    *(float4*)&g_pw[row*NN + t*4] = pw;
    if (t == 0) out_scores[row] = sestot*inv + g_Si[row] + g_Si[ROWS + row]
                                + g_Si[2*ROWS + row] + g_Si[3*ROWS + row] + b2p[0];
}

// ============ K4: context partials  g_cp[jh] = pw-slice @ emb ============
// grid (32 = 4 d x 8 j-splits, 16 i-tiles of 64). 256 thr. Single barrier;
// e tile in smem (loaded once), pw streamed via LDG + in-reg dup.
__global__ void __launch_bounds__(256) k_ctx() {
    __shared__ __align__(16) float e_s[64][80];    // 20 KB
    int t = threadIdx.x;
    int ig = t >> 3, dx = t & 7;
    int dt = blockIdx.x & 3, jh = blockIdx.x >> 2;
    int it = blockIdx.y;
    int i0 = it * 64;                  // global row
    int b  = it >> 3;
    int d0 = dt * 80;
    int j0 = jh * 64;                  // j within batch
    int dbase = dx * 10;
    int r0 = 2*ig, r1 = 2*ig + 1;

    // load e tile: 64 j x 80 d (1280 float4)
    #pragma unroll
    for (int pass = 0; pass < 5; pass++) {
        int idx = t + pass*256;
        int jr = idx / 20, dc = idx - jr*20;
        *(float4*)&e_s[jr][dc*4] =
            *(const float4*)&g_emb[(size_t)(b*NN + j0 + jr)*OBJ + d0 + dc*4];
    }
    __syncthreads();

    u64 acc0[5], acc1[5];
    #pragma unroll
    for (int q = 0; q < 5; q++) { acc0[q] = 0ull; acc1[q] = 0ull; }

    const float* pw0 = &g_pw[(size_t)(i0 + r0)*NN + j0];
    const float* pw1 = &g_pw[(size_t)(i0 + r1)*NN + j0];

    #pragma unroll 8
    for (int jk = 0; jk < 64; jk++) {
        float w0 = __ldg(pw0 + jk);
        float w1 = __ldg(pw1 + jk);
        u64 p0 = pk2(w0, w0);
        u64 p1 = pk2(w1, w1);
        #pragma unroll
        for (int q = 0; q < 5; q++) {
            u64 e2 = *(const u64*)&e_s[jk][dbase + 2*q];
            acc0[q] = ffma2(p0, e2, acc0[q]);
            acc1[q] = ffma2(p1, e2, acc1[q]);
        }
    }

    float* o0 = &g_cp[jh][(size_t)(i0 + r0)*OBJ + d0 + dbase];
    float* o1 = &g_cp[jh][(size_t)(i0 + r1)*OBJ + d0 + dbase];
    #pragma unroll
    for (int q = 0; q < 5; q++) {
        float x0, x1;
        upk2(x0, x1, acc0[q]);
        *(float2*)&o0[2*q] = make_float2(x0, x1);
        upk2(x0, x1, acc1[q]);
        *(float2*)&o1[2*q] = make_float2(x0, x1);
    }
}

// ============ K5: combine j-split partials ============
__global__ void __launch_bounds__(256) k_comb(float* __restrict__ out_ctx) {
    int idx = (blockIdx.x * 256 + threadIdx.x) * 4;      // over ROWS*OBJ floats
    float4 s = *(const float4*)&g_cp[0][idx];
    #pragma unroll
    for (int q = 1; q < 8; q++) {
        float4 v = *(const float4*)&g_cp[q][idx];
        s.x += v.x; s.y += v.y; s.z += v.z; s.w += v.w;
    }
    *(float4*)&out_ctx[idx] = s;
}

extern "C" void kernel_launch(void* const* d_in, const int* in_sizes, int n_in,
                              void* d_out, int out_size) {
    (void)in_sizes; (void)n_in; (void)out_size;
    const float* emb   = (const float*)d_in[0];
    const float* geom  = (const float*)d_in[1];
    const float* utter = (const float*)d_in[2];
    const float* W1    = (const float*)d_in[3];
    const float* b1    = (const float*)d_in[4];
    const float* W2    = (const float*)d_in[5];
    const float* b2    = (const float*)d_in[6];
    float* out = (float*)d_out;            // [0,1024): relation_scores; then context

    k_proj<<<256, 256>>>(emb, geom, utter, W1, b1, W2);
    {
        dim3 g(NN/64, NN/64, 2*BB);
        k_gemm<<<g, 256>>>();
    }
    k_soft<<<ROWS, 128>>>(b2, out);
    {
        dim3 g(32, 16);
        k_ctx<<<g, 256>>>();
    }
    k_comb<<<(ROWS*OBJ)/1024, 256>>>(out + ROWS);
}

// round 13
// speedup vs baseline: 1.2026x; 1.1654x over previous
#include <cuda_runtime.h>

#define BB   2
#define NN   512
#define OBJ  320
#define GEO  6
#define LANG 256
#define HID  256
#define ROWS (BB*NN)   // 1024

#define C2 0.3989423f
#define C4 -0.0664904f
#define TWO_C2 0.79788456f

typedef unsigned long long u64;

__device__ __forceinline__ u64 pk2(float lo, float hi) {
    u64 r; asm("mov.b64 %0, {%1, %2};" : "=l"(r) : "f"(lo), "f"(hi)); return r;
}
__device__ __forceinline__ void upk2(float& lo, float& hi, u64 v) {
    asm("mov.b64 {%0, %1}, %2;" : "=f"(lo), "=f"(hi) : "l"(v));
}
__device__ __forceinline__ u64 ffma2(u64 a, u64 b, u64 c) {
    u64 d; asm("fma.rn.f32x2 %0, %1, %2, %3;" : "=l"(d) : "l"(a), "l"(b), "l"(c)); return d;
}

// L2-resident scratch
__device__ float g_emb[ROWS*OBJ];      // normalized embeddings
__device__ float g_FAt[HID*ROWS];      // [h][i]: 2*c2*W2[h]*hi[i,h]
__device__ float g_FBt[HID*ROWS];      // [h][j]: hj[j,h]
__device__ float g_Si [4*ROWS];        // per-h-quarter partials
__device__ float g_Sj [4*ROWS];
__device__ float g_sc [2*ROWS*NN];     // cross-score K-half partials
__device__ float g_pw [ROWS*NN];       // softmax pair weights
__device__ float g_cp [8][ROWS*OBJ];   // context j-split partials

// ============ K1: norm(emb) + norm(utter)+hl + projections + Si/Sj ============
// grid 256 = 64 row-tiles (16 rows) x 4 h-quarters (64 h). 256 threads.
#define EPITCH 324
__global__ void __launch_bounds__(256) k_proj(const float* __restrict__ emb_raw,
                                              const float* __restrict__ geom,
                                              const float* __restrict__ utter,
                                              const float* __restrict__ W1,
                                              const float* __restrict__ b1,
                                              const float* __restrict__ W2) {
    __shared__ __align__(16) float e4[16*EPITCH];  // 20.7 KB staged rows
    __shared__ __align__(16) float2 ep[OBJ][8];    // 20 KB row-pairs
    __shared__ __align__(16) float2 gp[GEO][8];
    __shared__ float ls[LANG];
    __shared__ float redl[8];
    __shared__ float hlp[4][64];
    __shared__ float red_si[8][4], red_sj[8][4];

    int bx = blockIdx.x;
    int rowtile = bx >> 2, hq = bx & 3;
    int row0 = rowtile * 16;
    int h0 = hq * 64;
    int b = row0 >> 9;
    int t = threadIdx.x;
    int lane = t & 31, warp = t >> 5;
    int hh = t & 63, rp2 = t >> 6;                 // h-index, 2-row-pair group
    int h = h0 + hh;

    // stage raw emb rows (coalesced float4)
    {
        const float4* src = (const float4*)(emb_raw + row0*OBJ);
        for (int idx = t; idx < 16*80; idx += 256) {
            int r = idx / 80, c = idx - r*80;
            *(float4*)&e4[r*EPITCH + c*4] = src[idx];
        }
    }
    // utterance sum-of-squares
    float lv = utter[b*LANG + t];
    {
        float ss = lv*lv;
        #pragma unroll
        for (int o = 16; o; o >>= 1) ss += __shfl_xor_sync(0xffffffffu, ss, o);
        if (lane == 0) redl[warp] = ss;
    }
    __syncthreads();

    // normalize emb rows: warp w owns rows w, w+8
    #pragma unroll
    for (int rr = 0; rr < 2; rr++) {
        int r = warp + rr*8;
        float ss = 0.f;
        for (int d = lane; d < OBJ; d += 32) { float v = e4[r*EPITCH + d]; ss = fmaf(v, v, ss); }
        #pragma unroll
        for (int o = 16; o; o >>= 1) ss += __shfl_xor_sync(0xffffffffu, ss, o);
        float inv = rsqrtf(ss);
        float* gdst = g_emb + (row0 + r)*OBJ;
        for (int d = lane; d < OBJ; d += 32) {
            float v = e4[r*EPITCH + d] * inv;
            e4[r*EPITCH + d] = v;
            if (hq == 0) gdst[d] = v;
        }
    }
    // normalized utterance
    {
        float tot = 0.f;
        #pragma unroll
        for (int w = 0; w < 8; w++) tot += redl[w];
        ls[t] = lv * rsqrtf(tot);
    }
    __syncthreads();

    // hl partial: 4 threads per h, each sums 64 l's
    {
        float acc = (rp2 == 0) ? b1[h] : 0.f;
        const float* Wl = W1 + (size_t)(2*OBJ + GEO + rp2*64)*HID + h;
        #pragma unroll 8
        for (int l = 0; l < 64; l++) acc = fmaf(ls[rp2*64 + l], Wl[l*HID], acc);
        hlp[rp2][hh] = acc;
    }
    // build pair layouts
    for (int idx = t; idx < OBJ*8; idx += 256) {
        int d = idx >> 3, p = idx & 7;
        ep[d][p] = make_float2(e4[(2*p)*EPITCH + d], e4[(2*p+1)*EPITCH + d]);
    }
    if (t < GEO*8) {
        int d = t >> 3, p = t & 7;
        gp[d][p] = make_float2(geom[(row0 + 2*p)*GEO + d], geom[(row0 + 2*p + 1)*GEO + d]);
    }
    __syncthreads();

    float hlv = (hlp[0][hh] + hlp[1][hh]) + (hlp[2][hh] + hlp[3][hh]);

    // main projection: thread handles 2 row-pairs for its h
    u64 ai[2], aj[2];
    ai[0] = ai[1] = aj[0] = aj[1] = 0ull;
    const float* Wi = W1 + h;
    const float* Wj = W1 + OBJ*HID + h;
    #pragma unroll 4
    for (int d = 0; d < OBJ; d++) {
        float wi = Wi[d*HID];
        float wj = Wj[d*HID];
        u64 wip = pk2(wi, wi), wjp = pk2(wj, wj);
        ulonglong2 E = *(const ulonglong2*)&ep[d][rp2*2];
        ai[0] = ffma2(E.x, wip, ai[0]);  aj[0] = ffma2(E.x, wjp, aj[0]);
        ai[1] = ffma2(E.y, wip, ai[1]);  aj[1] = ffma2(E.y, wjp, aj[1]);
    }
    const float* Wg = W1 + 2*OBJ*HID + h;
    #pragma unroll
    for (int g = 0; g < GEO; g++) {
        float wg = Wg[g*HID];
        u64 wgp = pk2(wg, wg), wgm = pk2(-wg, -wg);
        ulonglong2 G = *(const ulonglong2*)&gp[g][rp2*2];
        ai[0] = ffma2(G.x, wgm, ai[0]);  aj[0] = ffma2(G.x, wgp, aj[0]);
        ai[1] = ffma2(G.y, wgm, ai[1]);  aj[1] = ffma2(G.y, wgp, aj[1]);
    }

    // epilogue: features + quarter partial reductions
    float w2v = W2[h];
    float sir[4], sjr[4];
    #pragma unroll
    for (int p = 0; p < 2; p++) {
        int P = rp2*2 + p;
        float a0, a1, j0v, j1v;
        upk2(a0, a1, ai[p]);
        upk2(j0v, j1v, aj[p]);
        float hv0 = a0 + hlv, hv1 = a1 + hlv;
        *(float2*)&g_FAt[h*ROWS + row0 + 2*P] = make_float2(TWO_C2*w2v*hv0, TWO_C2*w2v*hv1);
        *(float2*)&g_FBt[h*ROWS + row0 + 2*P] = make_float2(j0v, j1v);
        float u0 = hv0*hv0, u1 = hv1*hv1;
        sir[2*p]   = w2v * fmaf(u0, fmaf(C4, u0, C2), 0.5f*hv0);
        sir[2*p+1] = w2v * fmaf(u1, fmaf(C4, u1, C2), 0.5f*hv1);
        float v0 = j0v*j0v, v1 = j1v*j1v;
        sjr[2*p]   = w2v * fmaf(v0, fmaf(C4, v0, C2), 0.5f*j0v);
        sjr[2*p+1] = w2v * fmaf(v1, fmaf(C4, v1, C2), 0.5f*j1v);
    }
    #pragma unroll
    for (int lr = 0; lr < 4; lr++) {
        float si = sir[lr], sj = sjr[lr];
        #pragma unroll
        for (int o = 16; o; o >>= 1) {
            si += __shfl_xor_sync(0xffffffffu, si, o);
            sj += __shfl_xor_sync(0xffffffffu, sj, o);
        }
        if (lane == 0) { red_si[warp][lr] = si; red_sj[warp][lr] = sj; }
    }
    __syncthreads();
    if (t < 16) {
        int r = t;
        int g2 = r >> 2, lr = r & 3;
        g_Si[hq*ROWS + row0 + r] = red_si[2*g2][lr] + red_si[2*g2+1][lr];
    } else if (t < 32) {
        int r = t - 16;
        int g2 = r >> 2, lr = r & 3;
        g_Sj[hq*ROWS + row0 + r] = red_sj[2*g2][lr] + red_sj[2*g2+1][lr];
    }
}

// ============ K2: cross GEMM K-split, B in double-buffered smem, A via L1 LDG ============
// grid (8, 8, 4): z = b*2 + kh. 64x64 tile, K=128 in 8 chunks of 16.
__global__ void __launch_bounds__(256) k_gemm() {
    __shared__ __align__(16) float Bs[2][16][64];  // 8 KB
    int t = threadIdx.x;
    int tx = t & 15, ty = t >> 4;
    int lk = t >> 4, l4 = (t & 15) * 4;
    int z  = blockIdx.z;
    int b  = z >> 1, kh = z & 1;
    int i0 = b*NN + blockIdx.y*64;
    int j0 = b*NN + blockIdx.x*64;
    int kbase0 = kh*128;

    const float* pb = g_FBt + (size_t)(kbase0 + lk)*ROWS + j0 + l4;
    const float* pa = g_FAt + (size_t)kbase0*ROWS + i0 + ty*4;

    u64 acc2[4][2];
    #pragma unroll
    for (int r = 0; r < 4; r++) { acc2[r][0] = 0ull; acc2[r][1] = 0ull; }

    float4 b4 = *(const float4*)pb;
    *(float4*)&Bs[0][lk][l4] = b4;
    __syncthreads();

    #pragma unroll 1
    for (int ch = 0; ch < 8; ch++) {
        int cur = ch & 1;
        if (ch < 7) b4 = *(const float4*)(pb + (size_t)(ch+1)*16*ROWS);
        #pragma unroll
        for (int k = 0; k < 16; k++) {
            float4 av = *(const float4*)(pa + (size_t)(ch*16 + k)*ROWS);
            ulonglong2 bP = *(const ulonglong2*)&Bs[cur][k][tx*4];
            u64 a0 = pk2(av.x, av.x);
            u64 a1 = pk2(av.y, av.y);
            u64 a2 = pk2(av.z, av.z);
            u64 a3 = pk2(av.w, av.w);
            acc2[0][0] = ffma2(a0, bP.x, acc2[0][0]);
            acc2[0][1] = ffma2(a0, bP.y, acc2[0][1]);
            acc2[1][0] = ffma2(a1, bP.x, acc2[1][0]);
            acc2[1][1] = ffma2(a1, bP.y, acc2[1][1]);
            acc2[2][0] = ffma2(a2, bP.x, acc2[2][0]);
            acc2[2][1] = ffma2(a2, bP.y, acc2[2][1]);
            acc2[3][0] = ffma2(a3, bP.x, acc2[3][0]);
            acc2[3][1] = ffma2(a3, bP.y, acc2[3][1]);
        }
        if (ch < 7) {
            *(float4*)&Bs[cur ^ 1][lk][l4] = b4;
            __syncthreads();
        }
    }

    int irow = i0 + ty*4;
    int jcol = blockIdx.x*64 + tx*4;
    float* dst = g_sc + (size_t)kh*ROWS*NN;
    #pragma unroll
    for (int r = 0; r < 4; r++) {
        float c0, c1, c2v, c3;
        upk2(c0, c1, acc2[r][0]);
        upk2(c2v, c3, acc2[r][1]);
        *(float4*)&dst[(irow + r)*NN + jcol] = make_float4(c0, c1, c2v, c3);
    }
}

// ============ K3: softmax + relation_scores ============
__global__ void k_soft(const float* __restrict__ b2p, float* __restrict__ out_scores) {
    int row = blockIdx.x;
    int b = row >> 9;
    int t = threadIdx.x;              // 128 threads, 4 cols each
    int lane = t & 31, warp = t >> 5;
    __shared__ float rm[4], rs[4], rss[4];

    float4 cA = *(const float4*)&g_sc[row*NN + t*4];
    float4 cB = *(const float4*)&g_sc[(size_t)ROWS*NN + row*NN + t*4];
    float s0 = cA.x + cB.x, s1 = cA.y + cB.y, s2 = cA.z + cB.z, s3 = cA.w + cB.w;
    #pragma unroll
    for (int q = 0; q < 4; q++) {
        float4 jq = *(const float4*)&g_Sj[q*ROWS + b*NN + t*4];
        s0 += jq.x; s1 += jq.y; s2 += jq.z; s3 += jq.w;
    }

    float m = fmaxf(fmaxf(s0, s1), fmaxf(s2, s3));
    #pragma unroll
    for (int o = 16; o; o >>= 1) m = fmaxf(m, __shfl_xor_sync(0xffffffffu, m, o));
    if (lane == 0) rm[warp] = m;
    __syncthreads();
    m = fmaxf(fmaxf(rm[0], rm[1]), fmaxf(rm[2], rm[3]));

    float e0 = __expf(s0 - m), e1 = __expf(s1 - m), e2 = __expf(s2 - m), e3 = __expf(s3 - m);
    float se  = (e0 + e1) + (e2 + e3);
    float ses = fmaf(e0, s0, fmaf(e1, s1, fmaf(e2, s2, e3*s3)));
    #pragma unroll
    for (int o = 16; o; o >>= 1) {
        se  += __shfl_xor_sync(0xffffffffu, se,  o);
        ses += __shfl_xor_sync(0xffffffffu, ses, o);
    }
    if (lane == 0) { rs[warp] = se; rss[warp] = ses; }
    __syncthreads();
    float setot  = (rs[0]  + rs[1])  + (rs[2]  + rs[3]);
    float sestot = (rss[0] + rss[1]) + (rss[2] + rss[3]);

    float inv = __fdividef(1.f, setot);
    float4 pw = make_float4(e0*inv, e1*inv, e2*inv, e3*inv);
    *(float4*)&g_pw[row*NN + t*4] = pw;
    if (t == 0) out_scores[row] = sestot*inv + g_Si[row] + g_Si[ROWS + row]
                                + g_Si[2*ROWS + row] + g_Si[3*ROWS + row] + b2p[0];
}

// ============ K4: context partials  g_cp[jh] = pw-slice @ emb ============
// grid (40 = 5 d-tiles x 8 j-splits, 16 i-tiles of 64) = 640 CTAs, 256 thr.
// e tile bank-swizzled (4-float gap after col 32, pitch 68); pw tile in smem
// pitch 68 (8-bank row spacing -> broadcast reads conflict-free). Zero inner
// barriers, zero inner LDGs.
#define CPITCH 68
__global__ void __launch_bounds__(256) k_ctx() {
    __shared__ __align__(16) float e_s [64*CPITCH];   // 17.4 KB
    __shared__ __align__(16) float pw_s[64*CPITCH];   // 17.4 KB
    int t = threadIdx.x;
    int ig = t >> 3, dx = t & 7;
    int bx = blockIdx.x;
    int dt = bx % 5, jh = bx / 5;      // 5 d-tiles, 8 j-splits
    int it = blockIdx.y;
    int i0 = it * 64;                  // global row
    int b  = it >> 3;
    int d0 = dt * 64;
    int j0 = jh * 64;                  // j within batch
    int r0 = 2*ig, r1 = r0 + 1;
    int m0 = dx*8 + ((dx >> 2) << 2);  // swizzle: 8 threads -> 8 distinct bank groups

    // load e tile (64 j x 64 d, swizzled) + pw tile (64 i x 64 j)
    #pragma unroll
    for (int pass = 0; pass < 4; pass++) {
        int idx = t + pass*256;                  // float4 index, 1024 total
        int jr = idx >> 4, dc4 = (idx & 15) * 4; // 16 float4 per row
        int mc = dc4 + ((dc4 >= 32) ? 4 : 0);
        *(float4*)&e_s[jr*CPITCH + mc] =
            *(const float4*)&g_emb[(size_t)(b*NN + j0 + jr)*OBJ + d0 + dc4];
    }
    #pragma unroll
    for (int pass = 0; pass < 4; pass++) {
        int idx = t + pass*256;
        int pr = idx >> 4, pc = (idx & 15) * 4;
        *(float4*)&pw_s[pr*CPITCH + pc] =
            *(const float4*)&g_pw[(size_t)(i0 + pr)*NN + j0 + pc];
    }
    __syncthreads();

    u64 acc0[4], acc1[4];
    #pragma unroll
    for (int q = 0; q < 4; q++) { acc0[q] = 0ull; acc1[q] = 0ull; }

    #pragma unroll 8
    for (int jk = 0; jk < 64; jk++) {
        float w0 = pw_s[r0*CPITCH + jk];
        float w1 = pw_s[r1*CPITCH + jk];
        u64 p0 = pk2(w0, w0);
        u64 p1 = pk2(w1, w1);
        ulonglong2 eA = *(const ulonglong2*)&e_s[jk*CPITCH + m0];
        ulonglong2 eB = *(const ulonglong2*)&e_s[jk*CPITCH + m0 + 4];
        acc0[0] = ffma2(p0, eA.x, acc0[0]);
        acc0[1] = ffma2(p0, eA.y, acc0[1]);
        acc0[2] = ffma2(p0, eB.x, acc0[2]);
        acc0[3] = ffma2(p0, eB.y, acc0[3]);
        acc1[0] = ffma2(p1, eA.x, acc1[0]);
        acc1[1] = ffma2(p1, eA.y, acc1[1]);
        acc1[2] = ffma2(p1, eB.x, acc1[2]);
        acc1[3] = ffma2(p1, eB.y, acc1[3]);
    }

    float* o0 = &g_cp[jh][(size_t)(i0 + r0)*OBJ + d0 + dx*8];
    float* o1 = &g_cp[jh][(size_t)(i0 + r1)*OBJ + d0 + dx*8];
    {
        float x0, x1, x2, x3;
        upk2(x0, x1, acc0[0]); upk2(x2, x3, acc0[1]);
        *(float4*)&o0[0] = make_float4(x0, x1, x2, x3);
        upk2(x0, x1, acc0[2]); upk2(x2, x3, acc0[3]);
        *(float4*)&o0[4] = make_float4(x0, x1, x2, x3);
        upk2(x0, x1, acc1[0]); upk2(x2, x3, acc1[1]);
        *(float4*)&o1[0] = make_float4(x0, x1, x2, x3);
        upk2(x0, x1, acc1[2]); upk2(x2, x3, acc1[3]);
        *(float4*)&o1[4] = make_float4(x0, x1, x2, x3);
    }
}

// ============ K5: combine j-split partials ============
__global__ void __launch_bounds__(256) k_comb(float* __restrict__ out_ctx) {
    int idx = (blockIdx.x * 256 + threadIdx.x) * 4;      // over ROWS*OBJ floats
    float4 s = *(const float4*)&g_cp[0][idx];
    #pragma unroll
    for (int q = 1; q < 8; q++) {
        float4 v = *(const float4*)&g_cp[q][idx];
        s.x += v.x; s.y += v.y; s.z += v.z; s.w += v.w;
    }
    *(float4*)&out_ctx[idx] = s;
}

extern "C" void kernel_launch(void* const* d_in, const int* in_sizes, int n_in,
                              void* d_out, int out_size) {
    (void)in_sizes; (void)n_in; (void)out_size;
    const float* emb   = (const float*)d_in[0];
    const float* geom  = (const float*)d_in[1];
    const float* utter = (const float*)d_in[2];
    const float* W1    = (const float*)d_in[3];
    const float* b1    = (const float*)d_in[4];
    const float* W2    = (const float*)d_in[5];
    const float* b2    = (const float*)d_in[6];
    float* out = (float*)d_out;            // [0,1024): relation_scores; then context

    k_proj<<<256, 256>>>(emb, geom, utter, W1, b1, W2);
    {
        dim3 g(NN/64, NN/64, 2*BB);
        k_gemm<<<g, 256>>>();
    }
    k_soft<<<ROWS, 128>>>(b2, out);
    {
        dim3 g(40, 16);
        k_ctx<<<g, 256>>>();
    }
    k_comb<<<(ROWS*OBJ)/1024, 256>>>(out + ROWS);
}